// round 8
// baseline (speedup 1.0000x reference)
#include <cuda_runtime.h>
#include <cuda_fp16.h>
#include <cstdint>

#define C1 64
#define C2 128
#define C3 256
#define DD 128
#define TM 128

// ---------------- static device scratch (no allocs allowed) ----------------
__device__ __half g_y2h[(size_t)131072 * DD];    // level-2 merged features (fp16)
__device__ __half g_y3h[(size_t)30720 * DD];     // y3 = feats3 @ W3 (fp16)
__device__ int    g_perm1[420000 + 4096];
__device__ int    g_perm2[131072 + 4096];
__device__ __half g_B3h[8 * 8 * 4096];           // [bin][chunk][n][k swizzled] fp16
__device__ __half g_B2h[8 * 6 * 4096];
__device__ __half g_Bw3h[8 * 4096];              // W3 chunks for y3 GEMM
__device__ int    g_cnt1[8], g_cnt2[8];
__device__ int    g_st1[9], g_st2[9];
__device__ int    g_cur1[8], g_cur2[8];

// ---------------- helpers ----------------
__device__ __forceinline__ uint32_t smem_u32(const void* p) {
    uint32_t a;
    asm("{ .reg .u64 t; cvta.to.shared.u64 t, %1; cvt.u32.u64 %0, t; }" : "=r"(a) : "l"(p));
    return a;
}
__device__ __forceinline__ void cp16(void* dst_smem, const void* src) {
    uint32_t d = smem_u32(dst_smem);
    asm volatile("cp.async.ca.shared.global [%0], [%1], 16;" :: "r"(d), "l"(src) : "memory");
}
// cp.async with zero-fill: src-size 0 -> 16 bytes of zeros
__device__ __forceinline__ void cp16z(void* dst_smem, const void* src, uint32_t srcsize) {
    uint32_t d = smem_u32(dst_smem);
    asm volatile("cp.async.ca.shared.global [%0], [%1], 16, %2;"
                 :: "r"(d), "l"(src), "r"(srcsize) : "memory");
}
__device__ __forceinline__ void cp_commit() { asm volatile("cp.async.commit_group;" ::: "memory"); }
__device__ __forceinline__ void cp_wait0()  { asm volatile("cp.async.wait_group 0;" ::: "memory"); }

__device__ __forceinline__ uint32_t pk(float a, float b) {
    __half2 h = __floats2half2_rn(a, b);
    return *(uint32_t*)&h;
}
__device__ __forceinline__ void ldsm4(uint32_t* r, uint32_t addr) {
    asm volatile("ldmatrix.sync.aligned.m8n8.x4.shared.b16 {%0,%1,%2,%3}, [%4];"
                 : "=r"(r[0]), "=r"(r[1]), "=r"(r[2]), "=r"(r[3]) : "r"(addr));
}
__device__ __forceinline__ void mma_f16(float* c, const uint32_t* a, const uint32_t* b) {
    asm volatile(
        "mma.sync.aligned.m16n8k16.row.col.f32.f16.f16.f32 "
        "{%0,%1,%2,%3}, {%4,%5,%6,%7}, {%8,%9}, {%0,%1,%2,%3};\n"
        : "+f"(c[0]), "+f"(c[1]), "+f"(c[2]), "+f"(c[3])
        : "r"(a[0]), "r"(a[1]), "r"(a[2]), "r"(a[3]), "r"(b[0]), "r"(b[1]));
}

// swizzled half-index within a 128x32-half chunk tile (rows of 64B, XOR on 16B blocks)
__device__ __forceinline__ int swz_pos(int row, int kc) {
    return row * 32 + ((((kc >> 3) & 3) ^ ((row >> 1) & 3)) << 3) + (kc & 7);
}

// ---------------- prep: init perms, zero counters, convert W3 to fp16 tiles ----------------
__global__ void k_prep(int* perm1, int n1p, int* perm2, int n2p, int* cnt1, int* cnt2,
                       const float* __restrict__ W3, __half* Bw3h) {
    int i = blockIdx.x * blockDim.x + threadIdx.x;
    int stride = gridDim.x * blockDim.x;
    for (int j = i; j < n1p; j += stride) perm1[j] = -1;
    for (int j = i; j < n2p; j += stride) perm2[j] = -1;
    if (i < 8) { cnt1[i] = 0; cnt2[i] = 0; }
    for (int j = i; j < 256 * 128; j += stride) {
        int k = j >> 7, n = j & 127;
        int ch = k >> 5, kc = k & 31;
        Bw3h[ch * 4096 + swz_pos(n, kc)] = __float2half_rn(W3[(size_t)k * 128 + n]);
    }
}

__global__ void k_hist2(const int* __restrict__ off1, int n1,
                        const int* __restrict__ off2, int n2, int* cnt1, int* cnt2) {
    __shared__ int s[16];
    if (threadIdx.x < 16) s[threadIdx.x] = 0;
    __syncthreads();
    int stride = gridDim.x * blockDim.x;
    for (int i = blockIdx.x * blockDim.x + threadIdx.x; i < n1; i += stride) atomicAdd(&s[off1[i]], 1);
    for (int i = blockIdx.x * blockDim.x + threadIdx.x; i < n2; i += stride) atomicAdd(&s[8 + off2[i]], 1);
    __syncthreads();
    if (threadIdx.x < 8) atomicAdd(&cnt1[threadIdx.x], s[threadIdx.x]);
    else if (threadIdx.x < 16) atomicAdd(&cnt2[threadIdx.x - 8], s[threadIdx.x]);
}

__global__ void k_scan2(const int* cnt1, int* st1, int* cur1,
                        const int* cnt2, int* st2, int* cur2) {
    if (threadIdx.x == 0) {
        int run = 0;
        for (int k = 0; k < 8; k++) { st1[k] = run; cur1[k] = run; run += ((cnt1[k] + TM - 1) / TM) * TM; }
        st1[8] = run;
        run = 0;
        for (int k = 0; k < 8; k++) { st2[k] = run; cur2[k] = run; run += ((cnt2[k] + TM - 1) / TM) * TM; }
        st2[8] = run;
    }
}

__global__ void k_scat2(const int* __restrict__ off1, int n1,
                        const int* __restrict__ off2, int n2,
                        int* cur1, int* cur2, int* perm1, int* perm2) {
    __shared__ int s_cnt[16], s_base[16];
    int i = blockIdx.x * blockDim.x + threadIdx.x;
    if (threadIdx.x < 16) s_cnt[threadIdx.x] = 0;
    __syncthreads();
    int slot = -1, r = 0;
    if (i < n1)            { slot = off1[i];          r = atomicAdd(&s_cnt[slot], 1); }
    else if (i < n1 + n2)  { slot = 8 + off2[i - n1]; r = atomicAdd(&s_cnt[slot], 1); }
    __syncthreads();
    if (threadIdx.x < 16) {
        int c = s_cnt[threadIdx.x];
        if (c) s_base[threadIdx.x] = (threadIdx.x < 8)
            ? atomicAdd(&cur1[threadIdx.x], c) : atomicAdd(&cur2[threadIdx.x - 8], c);
    }
    __syncthreads();
    if (slot >= 0) {
        if (slot < 8) perm1[s_base[slot] + r] = i;
        else          perm2[s_base[slot] + r] = i - n1;
    }
}

// build fp16 B tiles: B3 = [T3k ; W2] (K=256), B2 = [T2k ; W1] (K=192)
__global__ void k_build(const float* __restrict__ T2, const float* __restrict__ W1,
                        const float* __restrict__ T3, const float* __restrict__ W2,
                        __half* B2h, __half* B3h) {
    int idx = blockIdx.x * blockDim.x + threadIdx.x;
    const int NB3 = 8 * 256 * 128;
    if (idx < NB3) {
        int bin = idx / (256 * 128);
        int k = (idx >> 7) % 256;
        int n = idx & 127;
        float v = (k < 128) ? T3[((size_t)bin * 128 + k) * 128 + n] : W2[(size_t)(k - 128) * 128 + n];
        int ch = k >> 5, kc = k & 31;
        B3h[(bin * 8 + ch) * 4096 + swz_pos(n, kc)] = __float2half_rn(v);
    } else {
        idx -= NB3;
        if (idx >= 8 * 192 * 128) return;
        int bin = idx / (192 * 128);
        int k = (idx >> 7) % 192;
        int n = idx & 127;
        float v = (k < 128) ? T2[((size_t)bin * 128 + k) * 128 + n] : W1[(size_t)(k - 128) * 128 + n];
        int ch = k >> 5, kc = k & 31;
        B2h[(bin * 6 + ch) * 4096 + swz_pos(n, kc)] = __float2half_rn(v);
    }
}

// ---------------- main gather-GEMM (fp16 mma.sync m16n8k16) ----------------
// dynamic smem 32KB: A[2][8KB] at 0, B[2][8KB] at 16384
// HC: coarse (gathered) source is fp16 -> staged by cp.async; HO: output fp16
template <int KTOT, int CSRC, int CFINE, bool DENSE, bool HC, bool HO>
__global__ __launch_bounds__(256, 2) void k_gemm(
    const void* __restrict__ coarse_, const float* __restrict__ fine,
    const __half* __restrict__ Btiles, const int* __restrict__ perm,
    const int* __restrict__ parent, const int* __restrict__ starts,
    int nrows, int tile0, void* __restrict__ out_)
{
    constexpr int NC = KTOT / 32;
    constexpr int NCC = HC ? (CSRC / 32) : 0;   // chunks staged via cp.async (fp16 coarse)
    constexpr int CEB = HC ? 2 : 4;             // coarse element bytes
    extern __shared__ char smemc[];
    __shared__ int s_gid[128];
    __shared__ const char* s_pc[128];
    __shared__ const float* s_pf[128];
    __shared__ int s_starts[9];

    const int tid = threadIdx.x;
    const int base = (tile0 + blockIdx.x) * TM;

    if (DENSE) {
        if (tid < 128) {
            int gid = (base + tid < nrows) ? base + tid : -1;
            s_gid[tid] = gid;
            s_pc[tid] = (gid >= 0) ? (const char*)coarse_ + (size_t)gid * CSRC * CEB : nullptr;
        }
    } else {
        if (tid < 9) s_starts[tid] = starts[tid];
        if (tid < 128) {
            int gd = perm[base + tid];
            s_gid[tid] = gd;
            s_pc[tid] = (gd >= 0) ? (const char*)coarse_ + (size_t)parent[gd] * CSRC * CEB : nullptr;
            s_pf[tid] = (gd >= 0) ? fine + (size_t)gd * CFINE : nullptr;
        }
    }
    __syncthreads();

    const __half* Bt = Btiles;
    if (!DENSE) {
        if (base >= s_starts[8]) return;
        int kb = 0;
        while (kb < 7 && base >= s_starts[kb + 1]) kb++;
        Bt = Btiles + (size_t)kb * NC * 4096;
    }

    const uint32_t uA = smem_u32(smemc);
    const uint32_t uB = uA + 16384;

    // ---- staging ids: one thread = one (row, 16-element k segment) ----
    const int srow = tid >> 1, sseg = tid & 1;
    const char* pc = s_pc[srow];
    const float* pc32 = (const float*)pc;                  // !HC (dense)
    const __half* pch = (const __half*)pc;                 // HC
    const float* pf = DENSE ? nullptr : s_pf[srow];
    const int srx = (srow >> 1) & 3;
    const uint32_t sts0 = srow * 64 + (((sseg * 2)     ^ srx) << 4);
    const uint32_t sts1 = srow * 64 + (((sseg * 2 + 1) ^ srx) << 4);
    const uint32_t csz = pc ? 16u : 0u;                    // cp.async src-size (zero-fill pad rows)

    // ---- compute-lane fragment addressing ----
    const int warp = tid >> 5, lane = tid & 31;
    const int wm = warp & 1, wn = warp >> 1;
    const int alrow = (lane & 7) + ((lane >> 3) & 1) * 8;
    const int akb = lane >> 4;                 // 0/1 k-block offset
    uint32_t a_row[4]; int a_rx[4];
#pragma unroll
    for (int mt = 0; mt < 4; mt++) {
        int r = wm * 64 + mt * 16 + alrow;
        a_row[mt] = uA + r * 64;
        a_rx[mt] = (r >> 1) & 3;
    }
    const int blrow = (lane & 7) + ((lane >> 4) << 3);
    const int bkb = (lane >> 3) & 1;
    uint32_t b_row[2]; int b_rx[2];
#pragma unroll
    for (int p = 0; p < 2; p++) {
        int n = wn * 32 + p * 16 + blrow;
        b_row[p] = uB + n * 64;
        b_rx[p] = (n >> 1) & 3;
    }

    float4 vf0, vf1, vf2, vf3;      // fp32 staging regs (fine / dense-coarse chunks)

    // A chunk c via cp.async (fp16 coarse rows, zero-fill for pad rows)
#define CPA(c) { \
        const __half* sph = pch + (c) * 32 + sseg * 16; \
        const void* s0 = pc ? (const void*)sph       : (const void*)Bt; \
        const void* s1 = pc ? (const void*)(sph + 8) : (const void*)Bt; \
        char* ab = smemc + (uint32_t)((c) & 1) * 8192u; \
        cp16z(ab + sts0, s0, csz); \
        cp16z(ab + sts1, s1, csz); }

    // fp32 staging: LDG to regs (chunk fully in fine part, or dense coarse)
#define LDGA(c) { \
        const int kk = (c) * 32 + sseg * 16; \
        const float* sp; \
        if (!HC) sp = pc32 ? pc32 + kk : nullptr; \
        else     sp = pf ? pf + (kk - CSRC) : nullptr; \
        if (sp) { vf0 = *(const float4*)sp;       vf1 = *(const float4*)(sp + 4); \
                  vf2 = *(const float4*)(sp + 8); vf3 = *(const float4*)(sp + 12); } \
        else { vf0 = vf1 = vf2 = vf3 = make_float4(0.f, 0.f, 0.f, 0.f); } }

#define STSA(c) { \
        const uint32_t boff_ = (uint32_t)((c) & 1) * 8192u; \
        uint4 w0 = make_uint4(pk(vf0.x, vf0.y), pk(vf0.z, vf0.w), \
                              pk(vf1.x, vf1.y), pk(vf1.z, vf1.w)); \
        uint4 w1 = make_uint4(pk(vf2.x, vf2.y), pk(vf2.z, vf2.w), \
                              pk(vf3.x, vf3.y), pk(vf3.z, vf3.w)); \
        *(uint4*)(smemc + boff_ + sts0) = w0; \
        *(uint4*)(smemc + boff_ + sts1) = w1; }

    // ---- prologue: chunk-0 copies (A via cp.async if coarse) + B(0) ----
    if (NCC > 0) { CPA(0); } else { LDGA(0); }
    {
        const char* bs = (const char*)Bt;
        char* bd = smemc + 16384;
        cp16(bd + tid * 32, bs + tid * 32);
        cp16(bd + tid * 32 + 16, bs + tid * 32 + 16);
        cp_commit();
    }

    float acc[4][4][4] = {};

    for (int c = 0; c < NC; c++) {
        const uint32_t boff = (uint32_t)(c & 1) * 8192u;
        if (c >= NCC) STSA(c);                       // fp32 chunk: regs -> smem
        if (c + 1 < NC && c + 1 >= NCC) LDGA(c + 1); // prefetch next fp32 chunk
        // All copies for chunk c (A-coarse + B) complete, then make visible.
        cp_wait0();
        __syncthreads();
        // Issue chunk c+1 copies after the barrier; overlap with compute(c).
        if (c + 1 < NC) {
            const char* bs = (const char*)Bt + (size_t)(c + 1) * 8192;
            char* bd = smemc + 16384 + ((c + 1) & 1) * 8192;
            cp16(bd + tid * 32, bs + tid * 32);
            cp16(bd + tid * 32 + 16, bs + tid * 32 + 16);
            if (c + 1 < NCC) CPA(c + 1);
            cp_commit();
        }
        // ---- compute chunk c: 12 ldmatrix.x4 + 32 mma ----
#pragma unroll
        for (int kb16 = 0; kb16 < 2; kb16++) {
            const int klo = kb16 * 2;
            uint32_t bf[2][4];
#pragma unroll
            for (int p = 0; p < 2; p++)
                ldsm4(bf[p], b_row[p] + boff + (((klo + bkb) ^ b_rx[p]) << 4));
#pragma unroll
            for (int mt = 0; mt < 4; mt++) {
                uint32_t af[4];
                ldsm4(af, a_row[mt] + boff + (((klo + akb) ^ a_rx[mt]) << 4));
#pragma unroll
                for (int nt = 0; nt < 4; nt++)
                    mma_f16(acc[mt][nt], af, &bf[nt >> 1][(nt & 1) * 2]);
            }
        }
    }

    // ---- epilogue: scatter store ----
    const int g = lane >> 2, tg = lane & 3;
#pragma unroll
    for (int mt = 0; mt < 4; mt++) {
        int row = wm * 64 + mt * 16 + g;
        int g0 = s_gid[row], g1 = s_gid[row + 8];
#pragma unroll
        for (int nt = 0; nt < 4; nt++) {
            int col = wn * 32 + nt * 8 + tg * 2;
            if (HO) {
                __half* oh = (__half*)out_;
                if (g0 >= 0)
                    *(uint32_t*)(oh + (size_t)g0 * DD + col) = pk(acc[mt][nt][0], acc[mt][nt][1]);
                if (g1 >= 0)
                    *(uint32_t*)(oh + (size_t)g1 * DD + col) = pk(acc[mt][nt][2], acc[mt][nt][3]);
            } else {
                float* of = (float*)out_;
                if (g0 >= 0)
                    *(float2*)(of + (size_t)g0 * DD + col) = make_float2(acc[mt][nt][0], acc[mt][nt][1]);
                if (g1 >= 0)
                    *(float2*)(of + (size_t)g1 * DD + col) = make_float2(acc[mt][nt][2], acc[mt][nt][3]);
            }
        }
    }
#undef CPA
#undef LDGA
#undef STSA
}

// ---------------- launch ----------------
extern "C" void kernel_launch(void* const* d_in, const int* in_sizes, int n_in,
                              void* d_out, int out_size)
{
    const float* feats1  = (const float*)d_in[0];
    const float* feats2  = (const float*)d_in[1];
    const float* feats3  = (const float*)d_in[2];
    const int*   parent1 = (const int*)d_in[3];
    const int*   offset1 = (const int*)d_in[4];
    const int*   parent2 = (const int*)d_in[5];
    const int*   offset2 = (const int*)d_in[6];
    const float* W1 = (const float*)d_in[7];
    const float* W2 = (const float*)d_in[8];
    const float* W3 = (const float*)d_in[9];
    const float* T2 = (const float*)d_in[10];
    const float* T3 = (const float*)d_in[11];

    const int N1 = in_sizes[3];
    const int N2 = in_sizes[5];
    const int N3 = in_sizes[2] / C3;

    __half *y2h, *y3h, *B2h, *B3h, *Bw3h;
    int *perm1, *perm2, *cnt1, *cnt2, *st1, *st2, *cu1, *cu2;
    cudaGetSymbolAddress((void**)&y2h, g_y2h);
    cudaGetSymbolAddress((void**)&y3h, g_y3h);
    cudaGetSymbolAddress((void**)&B2h, g_B2h);
    cudaGetSymbolAddress((void**)&B3h, g_B3h);
    cudaGetSymbolAddress((void**)&Bw3h, g_Bw3h);
    cudaGetSymbolAddress((void**)&perm1, g_perm1);
    cudaGetSymbolAddress((void**)&perm2, g_perm2);
    cudaGetSymbolAddress((void**)&cnt1, g_cnt1);
    cudaGetSymbolAddress((void**)&cnt2, g_cnt2);
    cudaGetSymbolAddress((void**)&st1, g_st1);
    cudaGetSymbolAddress((void**)&st2, g_st2);
    cudaGetSymbolAddress((void**)&cu1, g_cur1);
    cudaGetSymbolAddress((void**)&cu2, g_cur2);

    const int tiles1 = (N1 + TM - 1) / TM + 8;
    const int tiles2 = (N2 + TM - 1) / TM + 8;
    const int n1p = tiles1 * TM;
    const int n2p = tiles2 * TM;
    const int tiles3 = (N3 + TM - 1) / TM;
    const int t3a = (tiles3 + 1) / 2, t3b = tiles3 - t3a;

    // launches 1-3: prep chain
    k_prep<<<512, 256>>>(perm1, n1p, perm2, n2p, cnt1, cnt2, W3, Bw3h);
    k_hist2<<<512, 256>>>(offset1, N1, offset2, N2, cnt1, cnt2);
    k_scan2<<<1, 32>>>(cnt1, st1, cu1, cnt2, st2, cu2);
    // launches 4,5: y3 = feats3 @ W3 -> fp16 (dense, split so ncu -s captures a GEMM)
    k_gemm<256, C3, 1, true, false, true><<<t3a, 256, 32768>>>(feats3, nullptr, Bw3h,
        nullptr, nullptr, nullptr, N3, 0, y3h);
    k_gemm<256, C3, 1, true, false, true><<<t3b, 256, 32768>>>(feats3, nullptr, Bw3h,
        nullptr, nullptr, nullptr, N3, t3a, y3h);
    // launches 6,7: scatter + B builds
    k_scat2<<<(N1 + N2 + 255) / 256, 256>>>(offset1, N1, offset2, N2, cu1, cu2, perm1, perm2);
    k_build<<<(8 * 256 * 128 + 8 * 192 * 128 + 255) / 256, 256>>>(T2, W1, T3, W2, B2h, B3h);
    // launch 8: y2 = gather_tconv(y3, T3) + feats2 @ W2 -> fp16
    k_gemm<256, C2, C2, false, true, true><<<tiles2, 256, 32768>>>(y3h, feats2, B3h,
        perm2, parent2, st2, 0, 0, y2h);
    // launch 9: out = gather_tconv(y2, T2) + feats1 @ W1 -> fp32
    k_gemm<192, C2, C1, false, true, false><<<tiles1, 256, 32768>>>(y2h, feats1, B2h,
        perm1, parent1, st1, 0, 0, d_out);
}

// round 9
// speedup vs baseline: 1.0772x; 1.0772x over previous
#include <cuda_runtime.h>
#include <cuda_fp16.h>
#include <cstdint>

#define C1 64
#define C2 128
#define C3 256
#define DD 128
#define TM 128

// ---------------- static device scratch (no allocs allowed) ----------------
__device__ __half g_y2h[(size_t)131072 * DD];    // level-2 merged features (fp16)
__device__ __half g_y3h[(size_t)30720 * DD];     // y3 = feats3 @ W3 (fp16)
__device__ int    g_perm1[420000 + 4096];
__device__ int    g_perm2[131072 + 4096];
__device__ __half g_B3h[8 * 8 * 4096];           // [bin][chunk][n][k swizzled] fp16
__device__ __half g_B2h[8 * 6 * 4096];
__device__ __half g_Bw3h[8 * 4096];              // W3 chunks for y3 GEMM
__device__ int    g_hpart[512 * 16];             // per-block hist partials
__device__ int    g_st1[9], g_st2[9];
__device__ int    g_cur1[8], g_cur2[8];

// ---------------- helpers ----------------
__device__ __forceinline__ uint32_t smem_u32(const void* p) {
    uint32_t a;
    asm("{ .reg .u64 t; cvta.to.shared.u64 t, %1; cvt.u32.u64 %0, t; }" : "=r"(a) : "l"(p));
    return a;
}
__device__ __forceinline__ void cp16(void* dst_smem, const void* src) {
    uint32_t d = smem_u32(dst_smem);
    asm volatile("cp.async.ca.shared.global [%0], [%1], 16;" :: "r"(d), "l"(src) : "memory");
}
// cp.async with zero-fill: src-size 0 -> 16 bytes of zeros
__device__ __forceinline__ void cp16z(void* dst_smem, const void* src, uint32_t srcsize) {
    uint32_t d = smem_u32(dst_smem);
    asm volatile("cp.async.ca.shared.global [%0], [%1], 16, %2;"
                 :: "r"(d), "l"(src), "r"(srcsize) : "memory");
}
__device__ __forceinline__ void cp_commit() { asm volatile("cp.async.commit_group;" ::: "memory"); }
__device__ __forceinline__ void cp_wait1()  { asm volatile("cp.async.wait_group 1;" ::: "memory"); }
__device__ __forceinline__ void cp_wait0()  { asm volatile("cp.async.wait_group 0;" ::: "memory"); }

__device__ __forceinline__ uint32_t pk(float a, float b) {
    __half2 h = __floats2half2_rn(a, b);
    return *(uint32_t*)&h;
}
__device__ __forceinline__ void ldsm4(uint32_t* r, uint32_t addr) {
    asm volatile("ldmatrix.sync.aligned.m8n8.x4.shared.b16 {%0,%1,%2,%3}, [%4];"
                 : "=r"(r[0]), "=r"(r[1]), "=r"(r[2]), "=r"(r[3]) : "r"(addr));
}
__device__ __forceinline__ void mma_f16(float* c, const uint32_t* a, const uint32_t* b) {
    asm volatile(
        "mma.sync.aligned.m16n8k16.row.col.f32.f16.f16.f32 "
        "{%0,%1,%2,%3}, {%4,%5,%6,%7}, {%8,%9}, {%0,%1,%2,%3};\n"
        : "+f"(c[0]), "+f"(c[1]), "+f"(c[2]), "+f"(c[3])
        : "r"(a[0]), "r"(a[1]), "r"(a[2]), "r"(a[3]), "r"(b[0]), "r"(b[1]));
}

// swizzled half-index within a 128x32-half chunk tile (rows of 64B, XOR on 16B blocks)
__device__ __forceinline__ int swz_pos(int row, int kc) {
    return row * 32 + ((((kc >> 3) & 3) ^ ((row >> 1) & 3)) << 3) + (kc & 7);
}

// ---------------- prep: init perms + W3 fp16 tiles + hist partials ----------------
__global__ void k_prep(int* perm1, int n1p, int* perm2, int n2p,
                       const int* __restrict__ off1, int n1,
                       const int* __restrict__ off2, int n2, int* hpart,
                       const float* __restrict__ W3, __half* Bw3h) {
    __shared__ int s[16];
    if (threadIdx.x < 16) s[threadIdx.x] = 0;
    __syncthreads();
    int i = blockIdx.x * blockDim.x + threadIdx.x;
    int stride = gridDim.x * blockDim.x;
    for (int j = i; j < n1p; j += stride) perm1[j] = -1;
    for (int j = i; j < n2p; j += stride) perm2[j] = -1;
    for (int j = i; j < 256 * 128; j += stride) {
        int k = j >> 7, n = j & 127;
        int ch = k >> 5, kc = k & 31;
        Bw3h[ch * 4096 + swz_pos(n, kc)] = __float2half_rn(W3[(size_t)k * 128 + n]);
    }
    for (int j = i; j < n1; j += stride) atomicAdd(&s[off1[j]], 1);
    for (int j = i; j < n2; j += stride) atomicAdd(&s[8 + off2[j]], 1);
    __syncthreads();
    if (threadIdx.x < 16) hpart[blockIdx.x * 16 + threadIdx.x] = s[threadIdx.x];
}

// sum hist partials + exclusive scan (tile-padded) + init cursors
__global__ void k_scan(const int* __restrict__ hpart,
                       int* st1, int* cur1, int* st2, int* cur2) {
    __shared__ int c[16];
    int tid = threadIdx.x;
    if (tid < 16) c[tid] = 0;
    __syncthreads();
    int bin = tid & 15, slice = tid >> 4;   // 256 threads: 16 slices x 16 bins
    int sum = 0;
    for (int b = slice; b < 512; b += 16) sum += hpart[b * 16 + bin];
    atomicAdd(&c[bin], sum);
    __syncthreads();
    if (tid == 0) {
        int run = 0;
        for (int k = 0; k < 8; k++) { st1[k] = run; cur1[k] = run; run += ((c[k] + TM - 1) / TM) * TM; }
        st1[8] = run;
        run = 0;
        for (int k = 0; k < 8; k++) { st2[k] = run; cur2[k] = run; run += ((c[8 + k] + TM - 1) / TM) * TM; }
        st2[8] = run;
    }
}

// merged: scatter perms (blocks < scatBlocks) + build fp16 B tiles (rest)
__global__ void k_scatbuild(const int* __restrict__ off1, int n1,
                            const int* __restrict__ off2, int n2,
                            int* cur1, int* cur2, int* perm1, int* perm2,
                            const float* __restrict__ T2, const float* __restrict__ W1,
                            const float* __restrict__ T3, const float* __restrict__ W2,
                            __half* B2h, __half* B3h, int scatBlocks) {
    if ((int)blockIdx.x < scatBlocks) {
        __shared__ int s_cnt[16], s_base[16];
        int i = blockIdx.x * blockDim.x + threadIdx.x;
        if (threadIdx.x < 16) s_cnt[threadIdx.x] = 0;
        __syncthreads();
        int slot = -1, r = 0;
        if (i < n1)           { slot = off1[i];          r = atomicAdd(&s_cnt[slot], 1); }
        else if (i < n1 + n2) { slot = 8 + off2[i - n1]; r = atomicAdd(&s_cnt[slot], 1); }
        __syncthreads();
        if (threadIdx.x < 16) {
            int c = s_cnt[threadIdx.x];
            if (c) s_base[threadIdx.x] = (threadIdx.x < 8)
                ? atomicAdd(&cur1[threadIdx.x], c) : atomicAdd(&cur2[threadIdx.x - 8], c);
        }
        __syncthreads();
        if (slot >= 0) {
            if (slot < 8) perm1[s_base[slot] + r] = i;
            else          perm2[s_base[slot] + r] = i - n1;
        }
    } else {
        int idx = (blockIdx.x - scatBlocks) * blockDim.x + threadIdx.x;
        const int NB3 = 8 * 256 * 128;
        if (idx < NB3) {
            int bin = idx / (256 * 128);
            int k = (idx >> 7) % 256;
            int n = idx & 127;
            float v = (k < 128) ? T3[((size_t)bin * 128 + k) * 128 + n] : W2[(size_t)(k - 128) * 128 + n];
            int ch = k >> 5, kc = k & 31;
            B3h[(bin * 8 + ch) * 4096 + swz_pos(n, kc)] = __float2half_rn(v);
        } else {
            idx -= NB3;
            if (idx >= 8 * 192 * 128) return;
            int bin = idx / (192 * 128);
            int k = (idx >> 7) % 192;
            int n = idx & 127;
            float v = (k < 128) ? T2[((size_t)bin * 128 + k) * 128 + n] : W1[(size_t)(k - 128) * 128 + n];
            int ch = k >> 5, kc = k & 31;
            B2h[(bin * 6 + ch) * 4096 + swz_pos(n, kc)] = __float2half_rn(v);
        }
    }
}

// ---------------- main gather-GEMM (fp16 mma.sync m16n8k16, 3-stage pipe) ----------------
// dynamic smem 48KB: A[3][8KB] at 0, B[3][8KB] at 24576
#define SMEM_DYN 49152
template <int KTOT, int CSRC, int CFINE, bool DENSE, bool HC, bool HO>
__global__ __launch_bounds__(256, 2) void k_gemm(
    const void* __restrict__ coarse_, const float* __restrict__ fine,
    const __half* __restrict__ Btiles, const int* __restrict__ perm,
    const int* __restrict__ parent, const int* __restrict__ starts,
    int nrows, int tile0, void* __restrict__ out_)
{
    constexpr int NC = KTOT / 32;
    constexpr int NCC = HC ? (CSRC / 32) : 0;   // chunks staged via cp.async (fp16 coarse)
    constexpr int CEB = HC ? 2 : 4;             // coarse element bytes
    extern __shared__ char smemc[];
    __shared__ int s_gid[128];
    __shared__ const char* s_pc[128];
    __shared__ const float* s_pf[128];
    __shared__ int s_starts[9];

    const int tid = threadIdx.x;
    const int base = (tile0 + blockIdx.x) * TM;

    if (DENSE) {
        if (tid < 128) {
            int gid = (base + tid < nrows) ? base + tid : -1;
            s_gid[tid] = gid;
            s_pc[tid] = (gid >= 0) ? (const char*)coarse_ + (size_t)gid * CSRC * CEB : nullptr;
        }
    } else {
        if (tid < 9) s_starts[tid] = starts[tid];
        if (tid < 128) {
            int gd = perm[base + tid];
            s_gid[tid] = gd;
            s_pc[tid] = (gd >= 0) ? (const char*)coarse_ + (size_t)parent[gd] * CSRC * CEB : nullptr;
            s_pf[tid] = (gd >= 0) ? fine + (size_t)gd * CFINE : nullptr;
        }
    }
    __syncthreads();

    const __half* Bt = Btiles;
    if (!DENSE) {
        if (base >= s_starts[8]) return;
        int kb = 0;
        while (kb < 7 && base >= s_starts[kb + 1]) kb++;
        Bt = Btiles + (size_t)kb * NC * 4096;
    }

    const uint32_t uA = smem_u32(smemc);
    const uint32_t uB = uA + 24576;

    // ---- staging ids: one thread = one (row, 16-element k segment) ----
    const int srow = tid >> 1, sseg = tid & 1;
    const char* pc = s_pc[srow];
    const float* pc32 = (const float*)pc;                  // !HC (dense)
    const __half* pch = (const __half*)pc;                 // HC
    const float* pf = DENSE ? nullptr : s_pf[srow];
    const int srx = (srow >> 1) & 3;
    const uint32_t sts0 = srow * 64 + (((sseg * 2)     ^ srx) << 4);
    const uint32_t sts1 = srow * 64 + (((sseg * 2 + 1) ^ srx) << 4);
    const uint32_t csz = pc ? 16u : 0u;                    // cp.async src-size (zero-fill pad rows)

    // ---- compute-lane fragment addressing ----
    const int warp = tid >> 5, lane = tid & 31;
    const int wm = warp & 1, wn = warp >> 1;
    const int alrow = (lane & 7) + ((lane >> 3) & 1) * 8;
    const int akb = lane >> 4;                 // 0/1 k-block offset
    uint32_t a_row[4]; int a_rx[4];
#pragma unroll
    for (int mt = 0; mt < 4; mt++) {
        int r = wm * 64 + mt * 16 + alrow;
        a_row[mt] = uA + r * 64;
        a_rx[mt] = (r >> 1) & 3;
    }
    const int blrow = (lane & 7) + ((lane >> 4) << 3);
    const int bkb = (lane >> 3) & 1;
    uint32_t b_row[2]; int b_rx[2];
#pragma unroll
    for (int p = 0; p < 2; p++) {
        int n = wn * 32 + p * 16 + blrow;
        b_row[p] = uB + n * 64;
        b_rx[p] = (n >> 1) & 3;
    }

    float4 vf0, vf1, vf2, vf3;      // fp32 staging regs (fine / dense-coarse chunks)

    // A chunk c via cp.async (fp16 coarse rows, zero-fill for pad rows)
#define CPA(c) { \
        const __half* sph = pch + (c) * 32 + sseg * 16; \
        const void* s0 = pc ? (const void*)sph       : (const void*)Bt; \
        const void* s1 = pc ? (const void*)(sph + 8) : (const void*)Bt; \
        char* ab = smemc + (uint32_t)((c) % 3) * 8192u; \
        cp16z(ab + sts0, s0, csz); \
        cp16z(ab + sts1, s1, csz); }

    // B chunk c via cp.async
#define CPB(c) { \
        const char* bs = (const char*)Bt + (size_t)(c) * 8192; \
        char* bd = smemc + 24576 + (uint32_t)((c) % 3) * 8192u; \
        cp16(bd + tid * 32, bs + tid * 32); \
        cp16(bd + tid * 32 + 16, bs + tid * 32 + 16); }

    // fp32 staging: LDG to regs (fine chunk, or dense coarse)
#define LDGA(c) { \
        const int kk = (c) * 32 + sseg * 16; \
        const float* sp; \
        if (!HC) sp = pc32 ? pc32 + kk : nullptr; \
        else     sp = pf ? pf + (kk - CSRC) : nullptr; \
        if (sp) { vf0 = *(const float4*)sp;       vf1 = *(const float4*)(sp + 4); \
                  vf2 = *(const float4*)(sp + 8); vf3 = *(const float4*)(sp + 12); } \
        else { vf0 = vf1 = vf2 = vf3 = make_float4(0.f, 0.f, 0.f, 0.f); } }

#define STSA(c) { \
        char* ab = smemc + (uint32_t)((c) % 3) * 8192u; \
        uint4 w0 = make_uint4(pk(vf0.x, vf0.y), pk(vf0.z, vf0.w), \
                              pk(vf1.x, vf1.y), pk(vf1.z, vf1.w)); \
        uint4 w1 = make_uint4(pk(vf2.x, vf2.y), pk(vf2.z, vf2.w), \
                              pk(vf3.x, vf3.y), pk(vf3.z, vf3.w)); \
        *(uint4*)(ab + sts0) = w0; \
        *(uint4*)(ab + sts1) = w1; }

    // ---- prologue: issue chunk 0 and chunk 1 copy groups ----
    if (NCC > 0) { CPA(0); } else { LDGA(0); }
    CPB(0); cp_commit();                        // group 0
    if (NC > 1) {
        if (1 < NCC) CPA(1);
        CPB(1); cp_commit();                    // group 1
    }

    float acc[4][4][4] = {};

#pragma unroll
    for (int c = 0; c < NC; c++) {
        const uint32_t boff = (uint32_t)(c % 3) * 8192u;
        if (c >= NCC) STSA(c);                       // fp32 chunk: regs -> smem
        if (c + 1 < NC && c + 1 >= NCC) LDGA(c + 1); // prefetch next fp32 chunk
        if (c + 1 < NC) cp_wait1(); else cp_wait0(); // group c complete
        __syncthreads();
        if (c + 2 < NC) {                            // issue chunk c+2 group
            if (c + 2 < NCC) CPA(c + 2);
            CPB(c + 2); cp_commit();
        }
        // ---- compute chunk c: 12 ldmatrix.x4 + 32 mma ----
#pragma unroll
        for (int kb16 = 0; kb16 < 2; kb16++) {
            const int klo = kb16 * 2;
            uint32_t bf[2][4];
#pragma unroll
            for (int p = 0; p < 2; p++)
                ldsm4(bf[p], b_row[p] + boff + (((klo + bkb) ^ b_rx[p]) << 4));
#pragma unroll
            for (int mt = 0; mt < 4; mt++) {
                uint32_t af[4];
                ldsm4(af, a_row[mt] + boff + (((klo + akb) ^ a_rx[mt]) << 4));
#pragma unroll
                for (int nt = 0; nt < 4; nt++)
                    mma_f16(acc[mt][nt], af, &bf[nt >> 1][(nt & 1) * 2]);
            }
        }
    }

    // ---- epilogue: scatter store ----
    const int g = lane >> 2, tg = lane & 3;
#pragma unroll
    for (int mt = 0; mt < 4; mt++) {
        int row = wm * 64 + mt * 16 + g;
        int g0 = s_gid[row], g1 = s_gid[row + 8];
#pragma unroll
        for (int nt = 0; nt < 4; nt++) {
            int col = wn * 32 + nt * 8 + tg * 2;
            if (HO) {
                __half* oh = (__half*)out_;
                if (g0 >= 0)
                    *(uint32_t*)(oh + (size_t)g0 * DD + col) = pk(acc[mt][nt][0], acc[mt][nt][1]);
                if (g1 >= 0)
                    *(uint32_t*)(oh + (size_t)g1 * DD + col) = pk(acc[mt][nt][2], acc[mt][nt][3]);
            } else {
                float* of = (float*)out_;
                if (g0 >= 0)
                    *(float2*)(of + (size_t)g0 * DD + col) = make_float2(acc[mt][nt][0], acc[mt][nt][1]);
                if (g1 >= 0)
                    *(float2*)(of + (size_t)g1 * DD + col) = make_float2(acc[mt][nt][2], acc[mt][nt][3]);
            }
        }
    }
#undef CPA
#undef CPB
#undef LDGA
#undef STSA
}

// ---------------- launch ----------------
extern "C" void kernel_launch(void* const* d_in, const int* in_sizes, int n_in,
                              void* d_out, int out_size)
{
    const float* feats1  = (const float*)d_in[0];
    const float* feats2  = (const float*)d_in[1];
    const float* feats3  = (const float*)d_in[2];
    const int*   parent1 = (const int*)d_in[3];
    const int*   offset1 = (const int*)d_in[4];
    const int*   parent2 = (const int*)d_in[5];
    const int*   offset2 = (const int*)d_in[6];
    const float* W1 = (const float*)d_in[7];
    const float* W2 = (const float*)d_in[8];
    const float* W3 = (const float*)d_in[9];
    const float* T2 = (const float*)d_in[10];
    const float* T3 = (const float*)d_in[11];

    const int N1 = in_sizes[3];
    const int N2 = in_sizes[5];
    const int N3 = in_sizes[2] / C3;

    __half *y2h, *y3h, *B2h, *B3h, *Bw3h;
    int *perm1, *perm2, *hpart, *st1, *st2, *cu1, *cu2;
    cudaGetSymbolAddress((void**)&y2h, g_y2h);
    cudaGetSymbolAddress((void**)&y3h, g_y3h);
    cudaGetSymbolAddress((void**)&B2h, g_B2h);
    cudaGetSymbolAddress((void**)&B3h, g_B3h);
    cudaGetSymbolAddress((void**)&Bw3h, g_Bw3h);
    cudaGetSymbolAddress((void**)&perm1, g_perm1);
    cudaGetSymbolAddress((void**)&perm2, g_perm2);
    cudaGetSymbolAddress((void**)&hpart, g_hpart);
    cudaGetSymbolAddress((void**)&st1, g_st1);
    cudaGetSymbolAddress((void**)&st2, g_st2);
    cudaGetSymbolAddress((void**)&cu1, g_cur1);
    cudaGetSymbolAddress((void**)&cu2, g_cur2);

    cudaFuncSetAttribute(k_gemm<256, C3, 1, true, false, true>,
                         cudaFuncAttributeMaxDynamicSharedMemorySize, SMEM_DYN);
    cudaFuncSetAttribute(k_gemm<256, C2, C2, false, true, true>,
                         cudaFuncAttributeMaxDynamicSharedMemorySize, SMEM_DYN);
    cudaFuncSetAttribute(k_gemm<192, C2, C1, false, true, false>,
                         cudaFuncAttributeMaxDynamicSharedMemorySize, SMEM_DYN);

    const int tiles1 = (N1 + TM - 1) / TM + 8;
    const int tiles2 = (N2 + TM - 1) / TM + 8;
    const int n1p = tiles1 * TM;
    const int n2p = tiles2 * TM;
    const int tiles3 = (N3 + TM - 1) / TM;
    const int scatBlocks = (N1 + N2 + 255) / 256;
    const int buildBlocks = (8 * 256 * 128 + 8 * 192 * 128) / 256;   // 1792

    // launch 1: perm init + W3 tiles + hist partials
    k_prep<<<512, 256>>>(perm1, n1p, perm2, n2p, offset1, N1, offset2, N2,
                         hpart, W3, Bw3h);
    // launch 2: sum partials + prefix scan
    k_scan<<<1, 256>>>(hpart, st1, cu1, st2, cu2);
    // launch 3: scatter perms + build B tiles (merged)
    k_scatbuild<<<scatBlocks + buildBlocks, 256>>>(offset1, N1, offset2, N2,
        cu1, cu2, perm1, perm2, T2, W1, T3, W2, B2h, B3h, scatBlocks);
    // launch 4: y3 = feats3 @ W3 -> fp16 (single full-occupancy wave)
    k_gemm<256, C3, 1, true, false, true><<<tiles3, 256, SMEM_DYN>>>(feats3, nullptr, Bw3h,
        nullptr, nullptr, nullptr, N3, 0, y3h);
    // launch 5 (ncu capture slot): y2 = gather_tconv(y3, T3) + feats2 @ W2 -> fp16
    k_gemm<256, C2, C2, false, true, true><<<tiles2, 256, SMEM_DYN>>>(y3h, feats2, B3h,
        perm2, parent2, st2, 0, 0, y2h);
    // launch 6: out = gather_tconv(y2, T2) + feats1 @ W1 -> fp32
    k_gemm<192, C2, C1, false, true, false><<<tiles1, 256, SMEM_DYN>>>(y2h, feats1, B2h,
        perm1, parent1, st1, 0, 0, d_out);
}

// round 10
// speedup vs baseline: 1.0806x; 1.0031x over previous
#include <cuda_runtime.h>
#include <cuda_fp16.h>
#include <cstdint>

#define C1 64
#define C2 128
#define C3 256
#define DD 128
#define TM 128

// ---------------- static device scratch (no allocs allowed) ----------------
__device__ __half g_y2h[(size_t)131072 * DD];    // level-2 merged features (fp16)
__device__ __half g_y3h[(size_t)30720 * DD];     // y3 = feats3 @ W3 (fp16)
__device__ int    g_perm1[420000 + 4096];
__device__ int    g_perm2[131072 + 4096];
__device__ __half g_B3h[8 * 8 * 4096];           // [bin][chunk][n][k swizzled] fp16
__device__ __half g_B2h[8 * 6 * 4096];
__device__ __half g_Bw3h[8 * 4096];              // W3 chunks for y3 GEMM
__device__ int    g_hpart[512 * 16];             // per-block hist partials
__device__ int    g_done;                        // prep completion counter
__device__ int    g_st1[9], g_st2[9];
__device__ int    g_cnt1[8], g_cnt2[8];
__device__ int    g_cur1[8], g_cur2[8];

// ---------------- helpers ----------------
__device__ __forceinline__ uint32_t smem_u32(const void* p) {
    uint32_t a;
    asm("{ .reg .u64 t; cvta.to.shared.u64 t, %1; cvt.u32.u64 %0, t; }" : "=r"(a) : "l"(p));
    return a;
}
__device__ __forceinline__ void cp16(void* dst_smem, const void* src) {
    uint32_t d = smem_u32(dst_smem);
    asm volatile("cp.async.ca.shared.global [%0], [%1], 16;" :: "r"(d), "l"(src) : "memory");
}
// cp.async with zero-fill: src-size 0 -> 16 bytes of zeros
__device__ __forceinline__ void cp16z(void* dst_smem, const void* src, uint32_t srcsize) {
    uint32_t d = smem_u32(dst_smem);
    asm volatile("cp.async.ca.shared.global [%0], [%1], 16, %2;"
                 :: "r"(d), "l"(src), "r"(srcsize) : "memory");
}
__device__ __forceinline__ void cp_commit() { asm volatile("cp.async.commit_group;" ::: "memory"); }
__device__ __forceinline__ void cp_wait2()  { asm volatile("cp.async.wait_group 2;" ::: "memory"); }
__device__ __forceinline__ void cp_wait1()  { asm volatile("cp.async.wait_group 1;" ::: "memory"); }
__device__ __forceinline__ void cp_wait0()  { asm volatile("cp.async.wait_group 0;" ::: "memory"); }

__device__ __forceinline__ uint32_t pk(float a, float b) {
    __half2 h = __floats2half2_rn(a, b);
    return *(uint32_t*)&h;
}
__device__ __forceinline__ void ldsm4(uint32_t* r, uint32_t addr) {
    asm volatile("ldmatrix.sync.aligned.m8n8.x4.shared.b16 {%0,%1,%2,%3}, [%4];"
                 : "=r"(r[0]), "=r"(r[1]), "=r"(r[2]), "=r"(r[3]) : "r"(addr));
}
__device__ __forceinline__ void mma_f16(float* c, const uint32_t* a, const uint32_t* b) {
    asm volatile(
        "mma.sync.aligned.m16n8k16.row.col.f32.f16.f16.f32 "
        "{%0,%1,%2,%3}, {%4,%5,%6,%7}, {%8,%9}, {%0,%1,%2,%3};\n"
        : "+f"(c[0]), "+f"(c[1]), "+f"(c[2]), "+f"(c[3])
        : "r"(a[0]), "r"(a[1]), "r"(a[2]), "r"(a[3]), "r"(b[0]), "r"(b[1]));
}

// swizzled half-index within a 128x32-half chunk tile (rows of 64B, XOR on 16B blocks)
__device__ __forceinline__ int swz_pos(int row, int kc) {
    return row * 32 + ((((kc >> 3) & 3) ^ ((row >> 1) & 3)) << 3) + (kc & 7);
}

// ---------------- prep: W3 fp16 tiles + hist partials + fused last-block scan ----------------
__global__ void k_prep(const int* __restrict__ off1, int n1,
                       const int* __restrict__ off2, int n2, int* hpart,
                       const float* __restrict__ W3, __half* Bw3h,
                       int* st1, int* cnt1, int* cur1,
                       int* st2, int* cnt2, int* cur2) {
    __shared__ int s[16];
    __shared__ int s_last;
    if (threadIdx.x < 16) s[threadIdx.x] = 0;
    __syncthreads();
    int i = blockIdx.x * blockDim.x + threadIdx.x;
    int stride = gridDim.x * blockDim.x;
    for (int j = i; j < 256 * 128; j += stride) {
        int k = j >> 7, n = j & 127;
        int ch = k >> 5, kc = k & 31;
        Bw3h[ch * 4096 + swz_pos(n, kc)] = __float2half_rn(W3[(size_t)k * 128 + n]);
    }
    for (int j = i; j < n1; j += stride) atomicAdd(&s[off1[j]], 1);
    for (int j = i; j < n2; j += stride) atomicAdd(&s[8 + off2[j]], 1);
    __syncthreads();
    if (threadIdx.x < 16) atomicExch(&hpart[blockIdx.x * 16 + threadIdx.x], s[threadIdx.x]);
    __syncthreads();
    if (threadIdx.x == 0) {
        __threadfence();
        s_last = (atomicAdd(&g_done, 1) == (int)gridDim.x - 1) ? 1 : 0;
    }
    __syncthreads();
    if (s_last) {
        // fused scan: 256 threads = 16 slices x 16 bins
        __threadfence();
        __shared__ int c[16];
        if (threadIdx.x < 16) c[threadIdx.x] = 0;
        __syncthreads();
        int bin = threadIdx.x & 15, slice = threadIdx.x >> 4;
        int sum = 0;
        for (int b = slice; b < (int)gridDim.x; b += 16) sum += hpart[b * 16 + bin];
        atomicAdd(&c[bin], sum);
        __syncthreads();
        if (threadIdx.x == 0) {
            int run = 0;
            for (int k = 0; k < 8; k++) {
                st1[k] = run; cur1[k] = run; cnt1[k] = c[k];
                run += ((c[k] + TM - 1) / TM) * TM;
            }
            st1[8] = run;
            run = 0;
            for (int k = 0; k < 8; k++) {
                st2[k] = run; cur2[k] = run; cnt2[k] = c[8 + k];
                run += ((c[8 + k] + TM - 1) / TM) * TM;
            }
            st2[8] = run;
            g_done = 0;                 // reset for next graph replay
        }
    }
}

// merged: scatter perms + build fp16 B tiles + pad-fill (last block)
__global__ void k_scatbuild(const int* __restrict__ off1, int n1,
                            const int* __restrict__ off2, int n2,
                            int* cur1, int* cur2, int* perm1, int* perm2,
                            const int* __restrict__ st1, const int* __restrict__ cnt1,
                            const int* __restrict__ st2, const int* __restrict__ cnt2,
                            int n1p, int n2p,
                            const float* __restrict__ T2, const float* __restrict__ W1,
                            const float* __restrict__ T3, const float* __restrict__ W2,
                            __half* B2h, __half* B3h, int scatBlocks, int buildBlocks) {
    int bid = blockIdx.x;
    if (bid < scatBlocks) {
        __shared__ int s_cnt[16], s_base[16];
        int i = bid * blockDim.x + threadIdx.x;
        if (threadIdx.x < 16) s_cnt[threadIdx.x] = 0;
        __syncthreads();
        int slot = -1, r = 0;
        if (i < n1)           { slot = off1[i];          r = atomicAdd(&s_cnt[slot], 1); }
        else if (i < n1 + n2) { slot = 8 + off2[i - n1]; r = atomicAdd(&s_cnt[slot], 1); }
        __syncthreads();
        if (threadIdx.x < 16) {
            int c = s_cnt[threadIdx.x];
            if (c) s_base[threadIdx.x] = (threadIdx.x < 8)
                ? atomicAdd(&cur1[threadIdx.x], c) : atomicAdd(&cur2[threadIdx.x - 8], c);
        }
        __syncthreads();
        if (slot >= 0) {
            if (slot < 8) perm1[s_base[slot] + r] = i;
            else          perm2[s_base[slot] + r] = i - n1;
        }
    } else if (bid < scatBlocks + buildBlocks) {
        int idx = (bid - scatBlocks) * blockDim.x + threadIdx.x;
        const int NB3 = 8 * 256 * 128;
        if (idx < NB3) {
            int bin = idx / (256 * 128);
            int k = (idx >> 7) % 256;
            int n = idx & 127;
            float v = (k < 128) ? T3[((size_t)bin * 128 + k) * 128 + n] : W2[(size_t)(k - 128) * 128 + n];
            int ch = k >> 5, kc = k & 31;
            B3h[(bin * 8 + ch) * 4096 + swz_pos(n, kc)] = __float2half_rn(v);
        } else {
            idx -= NB3;
            if (idx >= 8 * 192 * 128) return;
            int bin = idx / (192 * 128);
            int k = (idx >> 7) % 192;
            int n = idx & 127;
            float v = (k < 128) ? T2[((size_t)bin * 128 + k) * 128 + n] : W1[(size_t)(k - 128) * 128 + n];
            int ch = k >> 5, kc = k & 31;
            B2h[(bin * 6 + ch) * 4096 + swz_pos(n, kc)] = __float2half_rn(v);
        }
    } else {
        // pad-fill block: -1 into tile-padding slots of both perms
        for (int k = 0; k < 8; k++) {
            int lo = st1[k] + cnt1[k], hi = st1[k + 1];
            for (int j = lo + (int)threadIdx.x; j < hi; j += blockDim.x) perm1[j] = -1;
            lo = st2[k] + cnt2[k]; hi = st2[k + 1];
            for (int j = lo + (int)threadIdx.x; j < hi; j += blockDim.x) perm2[j] = -1;
        }
        for (int j = st1[8] + (int)threadIdx.x; j < n1p; j += blockDim.x) perm1[j] = -1;
        for (int j = st2[8] + (int)threadIdx.x; j < n2p; j += blockDim.x) perm2[j] = -1;
    }
}

// ---------------- main gather-GEMM (fp16 mma.sync m16n8k16, 4-stage pipe) ----------------
// dynamic smem 64KB: A[4][8KB] at 0, B[4][8KB] at 32768
#define SMEM_DYN 65536
template <int KTOT, int CSRC, int CFINE, bool DENSE, bool HC, bool HO>
__global__ __launch_bounds__(256, 2) void k_gemm(
    const void* __restrict__ coarse_, const float* __restrict__ fine,
    const __half* __restrict__ Btiles, const int* __restrict__ perm,
    const int* __restrict__ parent, const int* __restrict__ starts,
    int nrows, int tile0, void* __restrict__ out_)
{
    constexpr int NC = KTOT / 32;
    constexpr int NCC = HC ? (CSRC / 32) : 0;   // chunks staged via cp.async (fp16 coarse)
    constexpr int CEB = HC ? 2 : 4;             // coarse element bytes
    extern __shared__ char smemc[];
    __shared__ int s_gid[128];
    __shared__ const char* s_pc[128];
    __shared__ const float* s_pf[128];
    __shared__ int s_starts[9];

    const int tid = threadIdx.x;
    const int base = (tile0 + blockIdx.x) * TM;

    if (DENSE) {
        if (tid < 128) {
            int gid = (base + tid < nrows) ? base + tid : -1;
            s_gid[tid] = gid;
            s_pc[tid] = (gid >= 0) ? (const char*)coarse_ + (size_t)gid * CSRC * CEB : nullptr;
        }
    } else {
        if (tid < 9) s_starts[tid] = starts[tid];
        if (tid < 128) {
            int gd = perm[base + tid];
            s_gid[tid] = gd;
            s_pc[tid] = (gd >= 0) ? (const char*)coarse_ + (size_t)parent[gd] * CSRC * CEB : nullptr;
            s_pf[tid] = (gd >= 0) ? fine + (size_t)gd * CFINE : nullptr;
        }
    }
    __syncthreads();

    const __half* Bt = Btiles;
    if (!DENSE) {
        if (base >= s_starts[8]) return;
        int kb = 0;
        while (kb < 7 && base >= s_starts[kb + 1]) kb++;
        Bt = Btiles + (size_t)kb * NC * 4096;
    }

    const uint32_t uA = smem_u32(smemc);
    const uint32_t uB = uA + 32768;

    // ---- staging ids: one thread = one (row, 16-element k segment) ----
    const int srow = tid >> 1, sseg = tid & 1;
    const char* pc = s_pc[srow];
    const float* pc32 = (const float*)pc;                  // !HC (dense)
    const __half* pch = (const __half*)pc;                 // HC
    const float* pf = DENSE ? nullptr : s_pf[srow];
    const int srx = (srow >> 1) & 3;
    const uint32_t sts0 = srow * 64 + (((sseg * 2)     ^ srx) << 4);
    const uint32_t sts1 = srow * 64 + (((sseg * 2 + 1) ^ srx) << 4);
    const uint32_t csz = pc ? 16u : 0u;                    // cp.async src-size (zero-fill pad rows)

    // ---- compute-lane fragment addressing ----
    const int warp = tid >> 5, lane = tid & 31;
    const int wm = warp & 1, wn = warp >> 1;
    const int alrow = (lane & 7) + ((lane >> 3) & 1) * 8;
    const int akb = lane >> 4;                 // 0/1 k-block offset
    uint32_t a_row[4]; int a_rx[4];
#pragma unroll
    for (int mt = 0; mt < 4; mt++) {
        int r = wm * 64 + mt * 16 + alrow;
        a_row[mt] = uA + r * 64;
        a_rx[mt] = (r >> 1) & 3;
    }
    const int blrow = (lane & 7) + ((lane >> 4) << 3);
    const int bkb = (lane >> 3) & 1;
    uint32_t b_row[2]; int b_rx[2];
#pragma unroll
    for (int p = 0; p < 2; p++) {
        int n = wn * 32 + p * 16 + blrow;
        b_row[p] = uB + n * 64;
        b_rx[p] = (n >> 1) & 3;
    }

    float4 vf0, vf1, vf2, vf3;      // fp32 staging regs (fine / dense-coarse chunks)

    // A chunk c via cp.async (fp16 coarse rows, zero-fill for pad rows)
#define CPA(c) { \
        const __half* sph = pch + (c) * 32 + sseg * 16; \
        const void* s0 = pc ? (const void*)sph       : (const void*)Bt; \
        const void* s1 = pc ? (const void*)(sph + 8) : (const void*)Bt; \
        char* ab = smemc + (uint32_t)((c) & 3) * 8192u; \
        cp16z(ab + sts0, s0, csz); \
        cp16z(ab + sts1, s1, csz); }

    // B chunk c via cp.async
#define CPB(c) { \
        const char* bs = (const char*)Bt + (size_t)(c) * 8192; \
        char* bd = smemc + 32768 + (uint32_t)((c) & 3) * 8192u; \
        cp16(bd + tid * 32, bs + tid * 32); \
        cp16(bd + tid * 32 + 16, bs + tid * 32 + 16); }

    // fp32 staging: LDG to regs (fine chunk, or dense coarse)
#define LDGA(c) { \
        const int kk = (c) * 32 + sseg * 16; \
        const float* sp; \
        if (!HC) sp = pc32 ? pc32 + kk : nullptr; \
        else     sp = pf ? pf + (kk - CSRC) : nullptr; \
        if (sp) { vf0 = *(const float4*)sp;       vf1 = *(const float4*)(sp + 4); \
                  vf2 = *(const float4*)(sp + 8); vf3 = *(const float4*)(sp + 12); } \
        else { vf0 = vf1 = vf2 = vf3 = make_float4(0.f, 0.f, 0.f, 0.f); } }

#define STSA(c) { \
        char* ab = smemc + (uint32_t)((c) & 3) * 8192u; \
        uint4 w0 = make_uint4(pk(vf0.x, vf0.y), pk(vf0.z, vf0.w), \
                              pk(vf1.x, vf1.y), pk(vf1.z, vf1.w)); \
        uint4 w1 = make_uint4(pk(vf2.x, vf2.y), pk(vf2.z, vf2.w), \
                              pk(vf3.x, vf3.y), pk(vf3.z, vf3.w)); \
        *(uint4*)(ab + sts0) = w0; \
        *(uint4*)(ab + sts1) = w1; }

    // ---- prologue: issue copy groups for chunks 0,1,2 ----
#pragma unroll
    for (int k = 0; k < 3; k++) {
        if (k < NC) {
            if (k < NCC) { CPA(k); }
            else if (k == 0) { LDGA(0); }
            CPB(k);
            cp_commit();
        }
    }

    float acc[4][4][4] = {};

#pragma unroll
    for (int c = 0; c < NC; c++) {
        const uint32_t boff = (uint32_t)(c & 3) * 8192u;
        if (c >= NCC) STSA(c);                       // fp32 chunk: regs -> smem
        if (c + 1 < NC && c + 1 >= NCC) LDGA(c + 1); // prefetch next fp32 chunk
        if (c + 2 < NC) cp_wait2();                  // group c complete
        else if (c + 1 < NC) cp_wait1();
        else cp_wait0();
        __syncthreads();
        if (c + 3 < NC) {                            // issue chunk c+3 group
            if (c + 3 < NCC) CPA(c + 3);
            CPB(c + 3);
            cp_commit();
        }
        // ---- compute chunk c: 12 ldmatrix.x4 + 32 mma ----
#pragma unroll
        for (int kb16 = 0; kb16 < 2; kb16++) {
            const int klo = kb16 * 2;
            uint32_t bf[2][4];
#pragma unroll
            for (int p = 0; p < 2; p++)
                ldsm4(bf[p], b_row[p] + boff + (((klo + bkb) ^ b_rx[p]) << 4));
#pragma unroll
            for (int mt = 0; mt < 4; mt++) {
                uint32_t af[4];
                ldsm4(af, a_row[mt] + boff + (((klo + akb) ^ a_rx[mt]) << 4));
#pragma unroll
                for (int nt = 0; nt < 4; nt++)
                    mma_f16(acc[mt][nt], af, &bf[nt >> 1][(nt & 1) * 2]);
            }
        }
    }

    // ---- epilogue: scatter store ----
    const int g = lane >> 2, tg = lane & 3;
#pragma unroll
    for (int mt = 0; mt < 4; mt++) {
        int row = wm * 64 + mt * 16 + g;
        int g0 = s_gid[row], g1 = s_gid[row + 8];
#pragma unroll
        for (int nt = 0; nt < 4; nt++) {
            int col = wn * 32 + nt * 8 + tg * 2;
            if (HO) {
                __half* oh = (__half*)out_;
                if (g0 >= 0)
                    *(uint32_t*)(oh + (size_t)g0 * DD + col) = pk(acc[mt][nt][0], acc[mt][nt][1]);
                if (g1 >= 0)
                    *(uint32_t*)(oh + (size_t)g1 * DD + col) = pk(acc[mt][nt][2], acc[mt][nt][3]);
            } else {
                float* of = (float*)out_;
                if (g0 >= 0)
                    *(float2*)(of + (size_t)g0 * DD + col) = make_float2(acc[mt][nt][0], acc[mt][nt][1]);
                if (g1 >= 0)
                    *(float2*)(of + (size_t)g1 * DD + col) = make_float2(acc[mt][nt][2], acc[mt][nt][3]);
            }
        }
    }
#undef CPA
#undef CPB
#undef LDGA
#undef STSA
}

// ---------------- launch ----------------
extern "C" void kernel_launch(void* const* d_in, const int* in_sizes, int n_in,
                              void* d_out, int out_size)
{
    const float* feats1  = (const float*)d_in[0];
    const float* feats2  = (const float*)d_in[1];
    const float* feats3  = (const float*)d_in[2];
    const int*   parent1 = (const int*)d_in[3];
    const int*   offset1 = (const int*)d_in[4];
    const int*   parent2 = (const int*)d_in[5];
    const int*   offset2 = (const int*)d_in[6];
    const float* W1 = (const float*)d_in[7];
    const float* W2 = (const float*)d_in[8];
    const float* W3 = (const float*)d_in[9];
    const float* T2 = (const float*)d_in[10];
    const float* T3 = (const float*)d_in[11];

    const int N1 = in_sizes[3];
    const int N2 = in_sizes[5];
    const int N3 = in_sizes[2] / C3;

    __half *y2h, *y3h, *B2h, *B3h, *Bw3h;
    int *perm1, *perm2, *hpart, *st1, *st2, *cn1, *cn2, *cu1, *cu2;
    cudaGetSymbolAddress((void**)&y2h, g_y2h);
    cudaGetSymbolAddress((void**)&y3h, g_y3h);
    cudaGetSymbolAddress((void**)&B2h, g_B2h);
    cudaGetSymbolAddress((void**)&B3h, g_B3h);
    cudaGetSymbolAddress((void**)&Bw3h, g_Bw3h);
    cudaGetSymbolAddress((void**)&perm1, g_perm1);
    cudaGetSymbolAddress((void**)&perm2, g_perm2);
    cudaGetSymbolAddress((void**)&hpart, g_hpart);
    cudaGetSymbolAddress((void**)&st1, g_st1);
    cudaGetSymbolAddress((void**)&st2, g_st2);
    cudaGetSymbolAddress((void**)&cn1, g_cnt1);
    cudaGetSymbolAddress((void**)&cn2, g_cnt2);
    cudaGetSymbolAddress((void**)&cu1, g_cur1);
    cudaGetSymbolAddress((void**)&cu2, g_cur2);

    cudaFuncSetAttribute(k_gemm<256, C3, 1, true, false, true>,
                         cudaFuncAttributeMaxDynamicSharedMemorySize, SMEM_DYN);
    cudaFuncSetAttribute(k_gemm<256, C2, C2, false, true, true>,
                         cudaFuncAttributeMaxDynamicSharedMemorySize, SMEM_DYN);
    cudaFuncSetAttribute(k_gemm<192, C2, C1, false, true, false>,
                         cudaFuncAttributeMaxDynamicSharedMemorySize, SMEM_DYN);

    const int tiles1 = (N1 + TM - 1) / TM + 8;
    const int tiles2 = (N2 + TM - 1) / TM + 8;
    const int n1p = tiles1 * TM;
    const int n2p = tiles2 * TM;
    const int tiles3 = (N3 + TM - 1) / TM;
    const int scatBlocks = (N1 + N2 + 255) / 256;
    const int buildBlocks = (8 * 256 * 128 + 8 * 192 * 128) / 256;   // 1792

    // launch 1: W3 tiles + hist partials + fused scan (last block)
    k_prep<<<512, 256>>>(offset1, N1, offset2, N2, hpart, W3, Bw3h,
                         st1, cn1, cu1, st2, cn2, cu2);
    // launch 2: scatter perms + build B tiles + pad-fill (merged)
    k_scatbuild<<<scatBlocks + buildBlocks + 1, 256>>>(offset1, N1, offset2, N2,
        cu1, cu2, perm1, perm2, st1, cn1, st2, cn2, n1p, n2p,
        T2, W1, T3, W2, B2h, B3h, scatBlocks, buildBlocks);
    // launch 3: y3 = feats3 @ W3 -> fp16
    k_gemm<256, C3, 1, true, false, true><<<tiles3, 256, SMEM_DYN>>>(feats3, nullptr, Bw3h,
        nullptr, nullptr, nullptr, N3, 0, y3h);
    // launch 4 (ncu capture slot): y2 = gather_tconv(y3, T3) + feats2 @ W2 -> fp16
    k_gemm<256, C2, C2, false, true, true><<<tiles2, 256, SMEM_DYN>>>(y3h, feats2, B3h,
        perm2, parent2, st2, 0, 0, y2h);
    // launch 5: out = gather_tconv(y2, T2) + feats1 @ W1 -> fp32
    k_gemm<192, C2, C1, false, true, false><<<tiles1, 256, SMEM_DYN>>>(y2h, feats1, B2h,
        perm1, parent1, st1, 0, 0, d_out);
}